// round 4
// baseline (speedup 1.0000x reference)
#include <cuda_runtime.h>
#include <math.h>

#define NN   30000
#define FIN  500
#define HIDN 16
#define OUTC 3
#define NE   960000

typedef unsigned long long ull;

// ---------------- scratch (device globals: no allocation allowed) ----------------
__device__ float g_h0[NN * HIDN];    // pooled conv features
__device__ float g_m1[NN * HIDN];    // (h0 @ W1) * dinv
__device__ float g_acc1[NN * HIDN];  // scatter accumulator layer 1
__device__ float g_m2[NN * 4];       // (out1 @ W2) * dinv (padded to 4)
__device__ float g_acc2[NN * 4];     // scatter accumulator layer 2
__device__ float g_dinv[NN];
__device__ int   g_deg[NN];

// ---------------- packed fp32x2 helpers (FFMA2 — PTX only) ----------------
__device__ __forceinline__ ull fma2(ull a, ull b, ull c) {
    ull d;
    asm("fma.rn.f32x2 %0, %1, %2, %3;" : "=l"(d) : "l"(a), "l"(b), "l"(c));
    return d;
}
__device__ __forceinline__ ull add2(ull a, ull b) {
    ull d;
    asm("add.rn.f32x2 %0, %1, %2;" : "=l"(d) : "l"(a), "l"(b));
    return d;
}
__device__ __forceinline__ void red4(float* p, float4 v) {
    asm volatile("red.global.add.v4.f32 [%0], {%1,%2,%3,%4};"
                 :: "l"(p), "f"(v.x), "f"(v.y), "f"(v.z), "f"(v.w) : "memory");
}

// ---------------- fused conv1+relu+conv2+relu+maxpool ----------------
// One block = one node. 128 threads = 8 half-warp "sets"; within a set the 16
// lanes each own one output channel o and all read the SAME y1 column
// (SMEM broadcast). Sliding 3-column window in registers; weights packed as
// f32x2 channel-pairs in registers.
__global__ void __launch_bounds__(128) conv_fused_kernel(
    const float* __restrict__ x,
    const float* __restrict__ w1, const float* __restrict__ b1,
    const float* __restrict__ w2, const float* __restrict__ b2)
{
    __shared__ __align__(16) float xs[FIN + 4];                // 1-based, zero pads at 0 and FIN+1
    __shared__ __align__(16) float y1s[(FIN + 2) * HIDN];      // [P][i], P=0..501, cols 0/501 zero
    __shared__ __align__(8)  float2 w2p[HIDN * 24];            // [o][tap*8 + i2] = {w[o][2*i2][tap], w[o][2*i2+1][tap]}
    __shared__ float redbuf[128];

    const int t = threadIdx.x;
    const int node = blockIdx.x;

    // load x row (500 floats = 125 float4; node*2000B is 16B-aligned)
    if (t < 125) {
        float4 v = reinterpret_cast<const float4*>(x + node * FIN)[t];
        xs[1 + 4 * t + 0] = v.x; xs[1 + 4 * t + 1] = v.y;
        xs[1 + 4 * t + 2] = v.z; xs[1 + 4 * t + 3] = v.w;
    }
    if (t == 0) { xs[0] = 0.f; xs[FIN + 1] = 0.f; }
    if (t < HIDN) { y1s[t] = 0.f; y1s[(FIN + 1) * HIDN + t] = 0.f; }

    // pack conv2 weights into f32x2 channel pairs
    for (int idx = t; idx < HIDN * 24; idx += 128) {
        int o = idx / 24, r = idx % 24, tap = r >> 3, i2 = r & 7;
        w2p[idx] = make_float2(w2[o * 48 + (2 * i2) * 3 + tap],
                               w2[o * 48 + (2 * i2 + 1) * 3 + tap]);
    }

    const int ci = t & 15;  // constant per thread across the conv1 strided loop
    const float cw0 = __ldg(w1 + ci * 3 + 0);
    const float cw1 = __ldg(w1 + ci * 3 + 1);
    const float cw2 = __ldg(w1 + ci * 3 + 2);
    const float cb  = __ldg(b1 + ci);
    __syncthreads();

    // ---- conv1 + relu -> y1s[p+1][ci] ----
    for (int idx = t; idx < FIN * HIDN; idx += 128) {
        int p = idx >> 4;  // 0..499
        float v = fmaf(cw0, xs[p], fmaf(cw1, xs[p + 1], fmaf(cw2, xs[p + 2], cb)));
        y1s[(p + 1) * HIDN + ci] = fmaxf(v, 0.f);
    }
    __syncthreads();

    // ---- conv2 + relu + max over positions ----
    const int o      = t & 15;
    const int set    = t >> 4;           // 0..7
    const int pstart = set * 63;
    const int pend   = (pstart + 63 < FIN) ? (pstart + 63) : FIN;  // last set = 59

    ull wv[24];
    {
        const ull* wp = reinterpret_cast<const ull*>(w2p) + o * 24;
        #pragma unroll
        for (int j = 0; j < 24; j++) wv[j] = wp[j];
    }

    ull c0[8], c1[8], c2[8];
    float mx = -3.4e38f;

    auto loadcol = [&](ull (&c)[8], int P) {
        const ulonglong2* cp = reinterpret_cast<const ulonglong2*>(y1s + P * HIDN);
        ulonglong2 a = cp[0], b = cp[1], cc = cp[2], d = cp[3];
        c[0] = a.x; c[1] = a.y; c[2] = b.x; c[3] = b.y;
        c[4] = cc.x; c[5] = cc.y; c[6] = d.x; c[7] = d.y;
    };
    auto step = [&](ull (&A)[8], ull (&B)[8], ull (&C)[8]) {
        ull a0 = 0, a1 = 0, a2 = 0;  // 3 independent chains
        #pragma unroll
        for (int j = 0; j < 8; j++) {
            a0 = fma2(wv[j],      A[j], a0);
            a1 = fma2(wv[8 + j],  B[j], a1);
            a2 = fma2(wv[16 + j], C[j], a2);
        }
        ull sv = add2(add2(a0, a1), a2);
        float lo = __uint_as_float((unsigned)(sv & 0xffffffffull));
        float hi = __uint_as_float((unsigned)(sv >> 32));
        mx = fmaxf(mx, lo + hi);
    };

    // position p needs smem columns p, p+1, p+2 (1-based layout)
    loadcol(c0, pstart);
    loadcol(c1, pstart + 1);
    int p = pstart;
    const int ntrip = (pend - pstart) / 3;
    for (int it = 0; it < ntrip; it++) {
        loadcol(c2, p + 2); step(c0, c1, c2);
        loadcol(c0, p + 3); step(c1, c2, c0);
        loadcol(c1, p + 4); step(c2, c0, c1);
        p += 3;
    }
    for (; p < pend; p++) {  // scalar remainder (<=2 positions)
        float s = 0.f;
        #pragma unroll
        for (int j = 0; j < 24; j++) {
            float2 w = w2p[o * 24 + j];
            int tap = j >> 3, i2 = j & 7;
            s += w.x * y1s[(p + tap) * HIDN + 2 * i2]
               + w.y * y1s[(p + tap) * HIDN + 2 * i2 + 1];
        }
        mx = fmaxf(mx, s);
    }

    // cross-set max reduction; relu(b + max) == max_p relu(b + s_p)
    redbuf[t] = mx;
    __syncthreads();
    if (t < HIDN) {
        float m = redbuf[t];
        #pragma unroll
        for (int s2 = 1; s2 < 8; s2++) m = fmaxf(m, redbuf[t + 16 * s2]);
        g_h0[node * HIDN + t] = fmaxf(m + __ldg(b2 + t), 0.f);
    }
}

// ---------------- GCN kernels ----------------
__global__ void zero_kernel() {
    int i = blockIdx.x * blockDim.x + threadIdx.x;
    if (i < NN * HIDN) g_acc1[i] = 0.f;
    if (i < NN * 4)    g_acc2[i] = 0.f;
    if (i < NN)        g_deg[i]  = 0;
}

__global__ void deg_kernel(const int* __restrict__ ei) {
    int e = blockIdx.x * blockDim.x + threadIdx.x;
    if (e < NE) atomicAdd(&g_deg[ei[NE + e]], 1);
}

// m1[v][j] = dinv[v] * sum_i h0[v][i] * W1[i][j]
__global__ void m1_kernel(const float* __restrict__ w) {
    int gid = blockIdx.x * blockDim.x + threadIdx.x;
    if (gid >= NN * HIDN) return;
    int v = gid >> 4, j = gid & 15;
    float dinv = rsqrtf((float)g_deg[v] + 1.0f);   // +1 self-loop
    if (j == 0) g_dinv[v] = dinv;
    float s = 0.f;
    #pragma unroll
    for (int i = 0; i < HIDN; i++)
        s = fmaf(g_h0[v * HIDN + i], __ldg(w + i * HIDN + j), s);
    g_m1[gid] = s * dinv;
}

__global__ void scatter1_kernel(const int* __restrict__ ei) {
    int e = blockIdx.x * blockDim.x + threadIdx.x;
    if (e >= NE) return;
    int s = ei[e], d = ei[NE + e];
    const float4* m = reinterpret_cast<const float4*>(g_m1 + s * HIDN);
    float4 v0 = m[0], v1 = m[1], v2 = m[2], v3 = m[3];
    float* a = g_acc1 + d * HIDN;
    red4(a, v0); red4(a + 4, v1); red4(a + 8, v2); red4(a + 12, v3);
}

// out1 = relu(dinv*(acc1+m1) + b1g); m2 = (out1 @ W2g) * dinv
__global__ void out1m2_kernel(const float* __restrict__ gb1, const float* __restrict__ gw2) {
    int v = blockIdx.x * blockDim.x + threadIdx.x;
    if (v >= NN) return;
    float dinv = g_dinv[v];
    const float4* a = reinterpret_cast<const float4*>(g_acc1 + v * HIDN);
    const float4* m = reinterpret_cast<const float4*>(g_m1 + v * HIDN);
    float o1[HIDN];
    #pragma unroll
    for (int q = 0; q < 4; q++) {
        float4 av = a[q], mv = m[q];
        o1[4 * q + 0] = fmaxf(dinv * (av.x + mv.x) + __ldg(gb1 + 4 * q + 0), 0.f);
        o1[4 * q + 1] = fmaxf(dinv * (av.y + mv.y) + __ldg(gb1 + 4 * q + 1), 0.f);
        o1[4 * q + 2] = fmaxf(dinv * (av.z + mv.z) + __ldg(gb1 + 4 * q + 2), 0.f);
        o1[4 * q + 3] = fmaxf(dinv * (av.w + mv.w) + __ldg(gb1 + 4 * q + 3), 0.f);
    }
    float s0 = 0.f, s1 = 0.f, s2 = 0.f;
    #pragma unroll
    for (int j = 0; j < HIDN; j++) {
        float h = o1[j];
        s0 = fmaf(h, __ldg(gw2 + j * 3 + 0), s0);
        s1 = fmaf(h, __ldg(gw2 + j * 3 + 1), s1);
        s2 = fmaf(h, __ldg(gw2 + j * 3 + 2), s2);
    }
    reinterpret_cast<float4*>(g_m2)[v] = make_float4(s0 * dinv, s1 * dinv, s2 * dinv, 0.f);
}

__global__ void scatter2_kernel(const int* __restrict__ ei) {
    int e = blockIdx.x * blockDim.x + threadIdx.x;
    if (e >= NE) return;
    int s = ei[e], d = ei[NE + e];
    float4 v = reinterpret_cast<const float4*>(g_m2)[s];
    red4(g_acc2 + d * 4, v);
}

__global__ void final_kernel(const float* __restrict__ gb2, float* __restrict__ out) {
    int v = blockIdx.x * blockDim.x + threadIdx.x;
    if (v >= NN) return;
    float dinv = g_dinv[v];
    float4 a = reinterpret_cast<const float4*>(g_acc2)[v];
    float4 m = reinterpret_cast<const float4*>(g_m2)[v];
    float z0 = dinv * (a.x + m.x) + __ldg(gb2 + 0);
    float z1 = dinv * (a.y + m.y) + __ldg(gb2 + 1);
    float z2 = dinv * (a.z + m.z) + __ldg(gb2 + 2);
    float mx = fmaxf(z0, fmaxf(z1, z2));
    float l = logf(expf(z0 - mx) + expf(z1 - mx) + expf(z2 - mx));
    out[v * 3 + 0] = z0 - mx - l;
    out[v * 3 + 1] = z1 - mx - l;
    out[v * 3 + 2] = z2 - mx - l;
}

// ---------------- launch ----------------
extern "C" void kernel_launch(void* const* d_in, const int* in_sizes, int n_in,
                              void* d_out, int out_size) {
    const float* x   = (const float*)d_in[0];
    const float* c1w = (const float*)d_in[1];
    const float* c1b = (const float*)d_in[2];
    const float* c2w = (const float*)d_in[3];
    const float* c2b = (const float*)d_in[4];
    const float* g1w = (const float*)d_in[5];
    const float* g1b = (const float*)d_in[6];
    const float* g2w = (const float*)d_in[7];
    const float* g2b = (const float*)d_in[8];
    const int*   ei  = (const int*)d_in[9];
    float* out = (float*)d_out;

    zero_kernel<<<(NN * HIDN + 255) / 256, 256>>>();
    conv_fused_kernel<<<NN, 128>>>(x, c1w, c1b, c2w, c2b);
    deg_kernel<<<(NE + 255) / 256, 256>>>(ei);
    m1_kernel<<<(NN * HIDN + 255) / 256, 256>>>(g1w);
    scatter1_kernel<<<(NE + 255) / 256, 256>>>(ei);
    out1m2_kernel<<<(NN + 127) / 128, 128>>>(g1b, g2w);
    scatter2_kernel<<<(NE + 255) / 256, 256>>>(ei);
    final_kernel<<<(NN + 127) / 128, 128>>>(g2b, out);
}